// round 5
// baseline (speedup 1.0000x reference)
#include <cuda_runtime.h>

// Guided filter, RADIUS=8, EPS=0.01, (8,3,1024,1024) fp32.
// Two fused kernels (horizontal box + vertical sliding box, trail recompute).
// Horizontal box via chain-free block-sum decomposition:
//   box[8k+j] = suffix_{k-1}(j) + U_k + prefix_{k+1}(j+1)
// with lane-local prefixes and 16 INDEPENDENT shuffles per series
// (no warp-scan dependency chain).

#define W     1024
#define Hh    1024
#define IMGS  24
#define HW    (Hh * W)
#define TOTAL (IMGS * HW)
#define RAD   8
#define EPSF  0.01f
#define SEGR  32
#define SEGS  (Hh / SEGR)
#define TPB   128               // 4 warps; warp w owns cols [256w, 256w+255]
#define FULLM 0xffffffffu

__device__ __align__(16) float g_a[TOTAL];
__device__ __align__(16) float g_b[TOTAL];

// Load own 8 cols of one row; lane 0 also loads the 8 cols left of the warp
// strip into h[], lane 31 the 8 cols right of it (zero outside the image).
__device__ __forceinline__ void load_strip(const float* __restrict__ r, int C,
                                           int lane, float v[8], float h[8]) {
    int col0 = C + lane * 8;
    float4 p0 = *(const float4*)(r + col0);
    float4 p1 = *(const float4*)(r + col0 + 4);
    v[0]=p0.x; v[1]=p0.y; v[2]=p0.z; v[3]=p0.w;
    v[4]=p1.x; v[5]=p1.y; v[6]=p1.z; v[7]=p1.w;
    #pragma unroll
    for (int j = 0; j < 8; j++) h[j] = 0.0f;
    if (lane == 0) {
        if (C > 0) {
            float4 a = *(const float4*)(r + C - 8);
            float4 b = *(const float4*)(r + C - 4);
            h[0]=a.x; h[1]=a.y; h[2]=a.z; h[3]=a.w;
            h[4]=b.x; h[5]=b.y; h[6]=b.z; h[7]=b.w;
        }
    } else if (lane == 31) {
        if (C + 256 < W) {
            float4 a = *(const float4*)(r + C + 256);
            float4 b = *(const float4*)(r + C + 260);
            h[0]=a.x; h[1]=a.y; h[2]=a.z; h[3]=a.w;
            h[4]=b.x; h[5]=b.y; h[6]=b.z; h[7]=b.w;
        }
    }
}

// Accumulate (SGN=+1/-1) the 17-wide horizontal box sums of one value series
// w[8] (halo hw[8] on lanes 0/31) into s[8]. Chain-free neighbor exchange.
template<int SGN>
__device__ __forceinline__ void box_acc(const float w[8], const float hw[8],
                                        int lane, float s[8]) {
    float p[9];
    p[0] = 0.0f;
    #pragma unroll
    for (int j = 0; j < 8; j++) p[j + 1] = p[j] + w[j];
    float U = p[8];

    float sufL[8], preR[8];
    #pragma unroll
    for (int j = 0; j < 8; j++) {
        sufL[j] = __shfl_up_sync(FULLM, U - p[j], 1);
        preR[j] = __shfl_down_sync(FULLM, p[j + 1], 1);
    }
    if (lane == 0) {                 // left halo suffixes: hw[j..7]
        float acc = 0.0f;
        #pragma unroll
        for (int j = 7; j >= 0; j--) { acc += hw[j]; sufL[j] = acc; }
    }
    if (lane == 31) {                // right halo prefixes: hw[0..j]
        float acc = 0.0f;
        #pragma unroll
        for (int j = 0; j < 8; j++) { acc += hw[j]; preR[j] = acc; }
    }
    #pragma unroll
    for (int j = 0; j < 8; j++) {
        float b = (sufL[j] + U) + preR[j];
        if (SGN > 0) s[j] += b; else s[j] -= b;
    }
}

// Stage-A row visit: accumulate h-box of {x, y, x*x, x*y}.
template<int SGN>
__device__ __forceinline__ void visitA(const float* __restrict__ xr,
                                       const float* __restrict__ yr,
                                       int C, int lane,
                                       float s0[8], float s1[8],
                                       float s2[8], float s3[8]) {
    float vx[8], hx[8], vy[8], hy[8];
    load_strip(xr, C, lane, vx, hx);
    load_strip(yr, C, lane, vy, hy);
    box_acc<SGN>(vx, hx, lane, s0);
    box_acc<SGN>(vy, hy, lane, s1);
    {
        float t[8], ht[8];
        #pragma unroll
        for (int j = 0; j < 8; j++) { t[j] = vx[j] * vx[j]; ht[j] = hx[j] * hx[j]; }
        box_acc<SGN>(t, ht, lane, s2);
    }
    {
        float t[8], ht[8];
        #pragma unroll
        for (int j = 0; j < 8; j++) { t[j] = vx[j] * vy[j]; ht[j] = hx[j] * hy[j]; }
        box_acc<SGN>(t, ht, lane, s3);
    }
}

// Stage-B row visit: accumulate h-box of {a, b}.
template<int SGN>
__device__ __forceinline__ void visitB(const float* __restrict__ ar,
                                       const float* __restrict__ br,
                                       int C, int lane,
                                       float sa[8], float sb[8]) {
    float va[8], ha[8], vb[8], hb[8];
    load_strip(ar, C, lane, va, ha);
    load_strip(br, C, lane, vb, hb);
    box_acc<SGN>(va, ha, lane, sa);
    box_acc<SGN>(vb, hb, lane, sb);
}

// ---------------------------------------------------------------------------
__global__ void __launch_bounds__(TPB) kA(const float* __restrict__ x,
                                          const float* __restrict__ y) {
    int img  = blockIdx.y;
    int s    = blockIdx.x * SEGR;
    int warp = threadIdx.x >> 5;
    int lane = threadIdx.x & 31;
    int C    = warp << 8;
    int col0 = C + lane * 8;
    const float* xb = x + img * HW;
    const float* yb = y + img * HW;

    float s0[8], s1[8], s2[8], s3[8];
    #pragma unroll
    for (int j = 0; j < 8; j++) { s0[j]=0.f; s1[j]=0.f; s2[j]=0.f; s3[j]=0.f; }

    for (int r = max(0, s - RAD); r <= s + RAD; r++)
        visitA<+1>(xb + r * W, yb + r * W, C, lane, s0, s1, s2, s3);

    float nxv[8];
    #pragma unroll
    for (int j = 0; j < 8; j++) {
        int c = col0 + j;
        nxv[j] = (float)(min(W - 1, c + RAD) - max(0, c - RAD) + 1);
    }

    float* ga = g_a + img * HW;
    float* gb = g_b + img * HW;

    for (int o = s; o < s + SEGR; o++) {
        float ny = (float)(min(Hh - 1, o + RAD) - max(0, o - RAD) + 1);
        float ra[8], rb[8];
        #pragma unroll
        for (int j = 0; j < 8; j++) {
            float invN = __frcp_rn(nxv[j] * ny);
            float mx = s0[j] * invN, my = s1[j] * invN;
            float varx = fmaf(-mx, mx, s2[j] * invN);
            float cov  = fmaf(-mx, my, s3[j] * invN);
            float a = __fdividef(cov, varx + EPSF);
            ra[j] = a;
            rb[j] = fmaf(-a, mx, my);
        }
        #pragma unroll
        for (int q = 0; q < 2; q++) {
            float4 av, bv;
            av.x = ra[4*q+0]; av.y = ra[4*q+1]; av.z = ra[4*q+2]; av.w = ra[4*q+3];
            bv.x = rb[4*q+0]; bv.y = rb[4*q+1]; bv.z = rb[4*q+2]; bv.w = rb[4*q+3];
            *(float4*)(ga + o * W + col0 + 4*q) = av;
            *(float4*)(gb + o * W + col0 + 4*q) = bv;
        }

        int lead = o + RAD + 1, trail = o - RAD;
        if (lead < Hh)
            visitA<+1>(xb + lead * W, yb + lead * W, C, lane, s0, s1, s2, s3);
        if (trail >= 0)
            visitA<-1>(xb + trail * W, yb + trail * W, C, lane, s0, s1, s2, s3);
    }
}

// ---------------------------------------------------------------------------
__global__ void __launch_bounds__(TPB) kB(const float* __restrict__ x,
                                          float* __restrict__ out) {
    int img  = blockIdx.y;
    int s    = blockIdx.x * SEGR;
    int warp = threadIdx.x >> 5;
    int lane = threadIdx.x & 31;
    int C    = warp << 8;
    int col0 = C + lane * 8;
    const float* ab = g_a + img * HW;
    const float* bb = g_b + img * HW;
    const float* xb = x + img * HW;
    float* ob = out + img * HW;

    float sa[8], sb[8];
    #pragma unroll
    for (int j = 0; j < 8; j++) { sa[j]=0.f; sb[j]=0.f; }

    for (int r = max(0, s - RAD); r <= s + RAD; r++)
        visitB<+1>(ab + r * W, bb + r * W, C, lane, sa, sb);

    float nxv[8];
    #pragma unroll
    for (int j = 0; j < 8; j++) {
        int c = col0 + j;
        nxv[j] = (float)(min(W - 1, c + RAD) - max(0, c - RAD) + 1);
    }

    for (int o = s; o < s + SEGR; o++) {
        float ny = (float)(min(Hh - 1, o + RAD) - max(0, o - RAD) + 1);
        #pragma unroll
        for (int q = 0; q < 2; q++) {
            float4 xv = *(const float4*)(xb + o * W + col0 + 4*q);
            float xs[4] = {xv.x, xv.y, xv.z, xv.w};
            float os[4];
            #pragma unroll
            for (int j = 0; j < 4; j++) {
                int k = 4*q + j;
                float invN = __frcp_rn(nxv[k] * ny);
                os[j] = fmaf(sa[k] * invN, xs[j], sb[k] * invN);
            }
            float4 ov;
            ov.x = os[0]; ov.y = os[1]; ov.z = os[2]; ov.w = os[3];
            *(float4*)(ob + o * W + col0 + 4*q) = ov;
        }

        int lead = o + RAD + 1, trail = o - RAD;
        if (lead < Hh)
            visitB<+1>(ab + lead * W, bb + lead * W, C, lane, sa, sb);
        if (trail >= 0)
            visitB<-1>(ab + trail * W, bb + trail * W, C, lane, sa, sb);
    }
}

extern "C" void kernel_launch(void* const* d_in, const int* in_sizes, int n_in,
                              void* d_out, int out_size) {
    const float* x = (const float*)d_in[0];
    const float* y = (const float*)d_in[1];
    float* out = (float*)d_out;

    dim3 grid(SEGS, IMGS);
    kA<<<grid, TPB>>>(x, y);
    kB<<<grid, TPB>>>(x, out);
}

// round 6
// speedup vs baseline: 1.1735x; 1.1735x over previous
#include <cuda_runtime.h>

// Guided filter, RADIUS=8, EPS=0.01, (8,3,1024,1024) fp32.
// kA: raw-value warp exchange (32 shfl/visit), 24-wide register window,
//     4 series computed locally. kB: chain-free prefix exchange (R5 scheme).
// Both: vertical sliding box with exact trail recompute.

#define W     1024
#define Hh    1024
#define IMGS  24
#define HW    (Hh * W)
#define TOTAL (IMGS * HW)
#define RAD   8
#define EPSF  0.01f
#define SEGR  32
#define SEGS  (Hh / SEGR)
#define TPB   128               // 4 warps; warp w owns cols [256w, 256w+255]
#define FULLM 0xffffffffu

__device__ __align__(16) float g_a[TOTAL];
__device__ __align__(16) float g_b[TOTAL];

// Load own 8 cols of one row; lane 0 also loads the 8 cols left of the warp
// strip into h[], lane 31 the 8 cols right of it (zero outside the image).
__device__ __forceinline__ void load_strip(const float* __restrict__ r, int C,
                                           int lane, float v[8], float h[8]) {
    int col0 = C + lane * 8;
    float4 p0 = *(const float4*)(r + col0);
    float4 p1 = *(const float4*)(r + col0 + 4);
    v[0]=p0.x; v[1]=p0.y; v[2]=p0.z; v[3]=p0.w;
    v[4]=p1.x; v[5]=p1.y; v[6]=p1.z; v[7]=p1.w;
    #pragma unroll
    for (int j = 0; j < 8; j++) h[j] = 0.0f;
    if (lane == 0) {
        if (C > 0) {
            float4 a = *(const float4*)(r + C - 8);
            float4 b = *(const float4*)(r + C - 4);
            h[0]=a.x; h[1]=a.y; h[2]=a.z; h[3]=a.w;
            h[4]=b.x; h[5]=b.y; h[6]=b.z; h[7]=b.w;
        }
    } else if (lane == 31) {
        if (C + 256 < W) {
            float4 a = *(const float4*)(r + C + 256);
            float4 b = *(const float4*)(r + C + 260);
            h[0]=a.x; h[1]=a.y; h[2]=a.z; h[3]=a.w;
            h[4]=b.x; h[5]=b.y; h[6]=b.z; h[7]=b.w;
        }
    }
}

// Build 24-wide window w[0..23] (cols col0-8 .. col0+15) from own v[8] and
// halo h[8] via 16 independent shuffles.
__device__ __forceinline__ void window24(const float v[8], const float h[8],
                                         int lane, float w[24]) {
    #pragma unroll
    for (int j = 0; j < 8; j++) w[8 + j] = v[j];
    #pragma unroll
    for (int j = 0; j < 8; j++) {
        float t = __shfl_up_sync(FULLM, v[j], 1);
        w[j] = (lane == 0) ? h[j] : t;
    }
    #pragma unroll
    for (int j = 0; j < 8; j++) {
        float t = __shfl_down_sync(FULLM, v[j], 1);
        w[16 + j] = (lane == 31) ? h[j] : t;
    }
}

// Stage-A row visit: accumulate (SGN) h-box of {x, y, x*x, x*y} into s0..s3.
template<int SGN>
__device__ __forceinline__ void visitA(const float* __restrict__ xr,
                                       const float* __restrict__ yr,
                                       int C, int lane,
                                       float s0[8], float s1[8],
                                       float s2[8], float s3[8]) {
    float vx[8], hx[8], vy[8], hy[8];
    load_strip(xr, C, lane, vx, hx);
    load_strip(yr, C, lane, vy, hy);
    float wx[24], wy[24];
    window24(vx, hx, lane, wx);
    window24(vy, hy, lane, wy);

    float sx = 0.f, sy = 0.f, sxx = 0.f, sxy = 0.f;
    #pragma unroll
    for (int j = 0; j < 17; j++) {
        float a = wx[j], b = wy[j];
        sx += a; sy += b;
        sxx = fmaf(a, a, sxx);
        sxy = fmaf(a, b, sxy);
    }
    #pragma unroll
    for (int k = 0; k < 8; k++) {
        if (k > 0) {
            float ao = wx[k-1], bo = wy[k-1];
            float an = wx[k+16], bn = wy[k+16];
            sx  += an - ao;
            sy  += bn - bo;
            sxx += an*an - ao*ao;
            sxy += an*bn - ao*bo;
        }
        if (SGN > 0) { s0[k] += sx; s1[k] += sy; s2[k] += sxx; s3[k] += sxy; }
        else         { s0[k] -= sx; s1[k] -= sy; s2[k] -= sxx; s3[k] -= sxy; }
    }
}

// kB primitive (R5): chain-free prefix/suffix exchange per series.
template<int SGN>
__device__ __forceinline__ void box_acc(const float w[8], const float hw[8],
                                        int lane, float s[8]) {
    float p[9];
    p[0] = 0.0f;
    #pragma unroll
    for (int j = 0; j < 8; j++) p[j + 1] = p[j] + w[j];
    float U = p[8];

    float sufL[8], preR[8];
    #pragma unroll
    for (int j = 0; j < 8; j++) {
        sufL[j] = __shfl_up_sync(FULLM, U - p[j], 1);
        preR[j] = __shfl_down_sync(FULLM, p[j + 1], 1);
    }
    if (lane == 0) {
        float acc = 0.0f;
        #pragma unroll
        for (int j = 7; j >= 0; j--) { acc += hw[j]; sufL[j] = acc; }
    }
    if (lane == 31) {
        float acc = 0.0f;
        #pragma unroll
        for (int j = 0; j < 8; j++) { acc += hw[j]; preR[j] = acc; }
    }
    #pragma unroll
    for (int j = 0; j < 8; j++) {
        float b = (sufL[j] + U) + preR[j];
        if (SGN > 0) s[j] += b; else s[j] -= b;
    }
}

template<int SGN>
__device__ __forceinline__ void visitB(const float* __restrict__ ar,
                                       const float* __restrict__ br,
                                       int C, int lane,
                                       float sa[8], float sb[8]) {
    float va[8], ha[8], vb[8], hb[8];
    load_strip(ar, C, lane, va, ha);
    load_strip(br, C, lane, vb, hb);
    box_acc<SGN>(va, ha, lane, sa);
    box_acc<SGN>(vb, hb, lane, sb);
}

// ---------------------------------------------------------------------------
__global__ void __launch_bounds__(TPB) kA(const float* __restrict__ x,
                                          const float* __restrict__ y) {
    int img  = blockIdx.y;
    int s    = blockIdx.x * SEGR;
    int warp = threadIdx.x >> 5;
    int lane = threadIdx.x & 31;
    int C    = warp << 8;
    int col0 = C + lane * 8;
    const float* xb = x + img * HW;
    const float* yb = y + img * HW;

    float s0[8], s1[8], s2[8], s3[8];
    #pragma unroll
    for (int j = 0; j < 8; j++) { s0[j]=0.f; s1[j]=0.f; s2[j]=0.f; s3[j]=0.f; }

    for (int r = max(0, s - RAD); r <= s + RAD; r++)
        visitA<+1>(xb + r * W, yb + r * W, C, lane, s0, s1, s2, s3);

    float inv_nx[8];
    #pragma unroll
    for (int j = 0; j < 8; j++) {
        int c = col0 + j;
        inv_nx[j] = __frcp_rn((float)(min(W - 1, c + RAD) - max(0, c - RAD) + 1));
    }

    float* ga = g_a + img * HW;
    float* gb = g_b + img * HW;

    for (int o = s; o < s + SEGR; o++) {
        float inv_ny = __frcp_rn((float)(min(Hh - 1, o + RAD) - max(0, o - RAD) + 1));
        float ra[8], rb[8];
        #pragma unroll
        for (int j = 0; j < 8; j++) {
            float invN = inv_nx[j] * inv_ny;
            float mx = s0[j] * invN, my = s1[j] * invN;
            float varx = fmaf(-mx, mx, s2[j] * invN);
            float cov  = fmaf(-mx, my, s3[j] * invN);
            float a = __fdividef(cov, varx + EPSF);
            ra[j] = a;
            rb[j] = fmaf(-a, mx, my);
        }
        #pragma unroll
        for (int q = 0; q < 2; q++) {
            float4 av, bv;
            av.x = ra[4*q+0]; av.y = ra[4*q+1]; av.z = ra[4*q+2]; av.w = ra[4*q+3];
            bv.x = rb[4*q+0]; bv.y = rb[4*q+1]; bv.z = rb[4*q+2]; bv.w = rb[4*q+3];
            *(float4*)(ga + o * W + col0 + 4*q) = av;
            *(float4*)(gb + o * W + col0 + 4*q) = bv;
        }

        int lead = o + RAD + 1, trail = o - RAD;
        if (lead < Hh)
            visitA<+1>(xb + lead * W, yb + lead * W, C, lane, s0, s1, s2, s3);
        if (trail >= 0)
            visitA<-1>(xb + trail * W, yb + trail * W, C, lane, s0, s1, s2, s3);
    }
}

// ---------------------------------------------------------------------------
__global__ void __launch_bounds__(TPB) kB(const float* __restrict__ x,
                                          float* __restrict__ out) {
    int img  = blockIdx.y;
    int s    = blockIdx.x * SEGR;
    int warp = threadIdx.x >> 5;
    int lane = threadIdx.x & 31;
    int C    = warp << 8;
    int col0 = C + lane * 8;
    const float* ab = g_a + img * HW;
    const float* bb = g_b + img * HW;
    const float* xb = x + img * HW;
    float* ob = out + img * HW;

    float sa[8], sb[8];
    #pragma unroll
    for (int j = 0; j < 8; j++) { sa[j]=0.f; sb[j]=0.f; }

    for (int r = max(0, s - RAD); r <= s + RAD; r++)
        visitB<+1>(ab + r * W, bb + r * W, C, lane, sa, sb);

    float inv_nx[8];
    #pragma unroll
    for (int j = 0; j < 8; j++) {
        int c = col0 + j;
        inv_nx[j] = __frcp_rn((float)(min(W - 1, c + RAD) - max(0, c - RAD) + 1));
    }

    for (int o = s; o < s + SEGR; o++) {
        float inv_ny = __frcp_rn((float)(min(Hh - 1, o + RAD) - max(0, o - RAD) + 1));
        #pragma unroll
        for (int q = 0; q < 2; q++) {
            float4 xv = *(const float4*)(xb + o * W + col0 + 4*q);
            float xs[4] = {xv.x, xv.y, xv.z, xv.w};
            float os[4];
            #pragma unroll
            for (int j = 0; j < 4; j++) {
                int k = 4*q + j;
                float invN = inv_nx[k] * inv_ny;
                os[j] = fmaf(sa[k] * invN, xs[j], sb[k] * invN);
            }
            float4 ov;
            ov.x = os[0]; ov.y = os[1]; ov.z = os[2]; ov.w = os[3];
            *(float4*)(ob + o * W + col0 + 4*q) = ov;
        }

        int lead = o + RAD + 1, trail = o - RAD;
        if (lead < Hh)
            visitB<+1>(ab + lead * W, bb + lead * W, C, lane, sa, sb);
        if (trail >= 0)
            visitB<-1>(ab + trail * W, bb + trail * W, C, lane, sa, sb);
    }
}

extern "C" void kernel_launch(void* const* d_in, const int* in_sizes, int n_in,
                              void* d_out, int out_size) {
    const float* x = (const float*)d_in[0];
    const float* y = (const float*)d_in[1];
    float* out = (float*)d_out;

    dim3 grid(SEGS, IMGS);
    kA<<<grid, TPB>>>(x, y);
    kB<<<grid, TPB>>>(x, out);
}

// round 7
// speedup vs baseline: 1.2250x; 1.0439x over previous
#include <cuda_runtime.h>

// Guided filter, RADIUS=8, EPS=0.01, (8,3,1024,1024) fp32.
// kA: raw-value warp exchange (32 shfl/visit), 24-wide register window,
//     4 series computed locally. kB: chain-free prefix exchange.
// Both: vertical sliding box with exact trail recompute.
// R7: SEGR 32 -> 16 to double the grid (occupancy was grid-limited at 31%).

#define W     1024
#define Hh    1024
#define IMGS  24
#define HW    (Hh * W)
#define TOTAL (IMGS * HW)
#define RAD   8
#define EPSF  0.01f
#define SEGR  16
#define SEGS  (Hh / SEGR)
#define TPB   128               // 4 warps; warp w owns cols [256w, 256w+255]
#define FULLM 0xffffffffu

__device__ __align__(16) float g_a[TOTAL];
__device__ __align__(16) float g_b[TOTAL];

// Load own 8 cols of one row; lane 0 also loads the 8 cols left of the warp
// strip into h[], lane 31 the 8 cols right of it (zero outside the image).
__device__ __forceinline__ void load_strip(const float* __restrict__ r, int C,
                                           int lane, float v[8], float h[8]) {
    int col0 = C + lane * 8;
    float4 p0 = *(const float4*)(r + col0);
    float4 p1 = *(const float4*)(r + col0 + 4);
    v[0]=p0.x; v[1]=p0.y; v[2]=p0.z; v[3]=p0.w;
    v[4]=p1.x; v[5]=p1.y; v[6]=p1.z; v[7]=p1.w;
    #pragma unroll
    for (int j = 0; j < 8; j++) h[j] = 0.0f;
    if (lane == 0) {
        if (C > 0) {
            float4 a = *(const float4*)(r + C - 8);
            float4 b = *(const float4*)(r + C - 4);
            h[0]=a.x; h[1]=a.y; h[2]=a.z; h[3]=a.w;
            h[4]=b.x; h[5]=b.y; h[6]=b.z; h[7]=b.w;
        }
    } else if (lane == 31) {
        if (C + 256 < W) {
            float4 a = *(const float4*)(r + C + 256);
            float4 b = *(const float4*)(r + C + 260);
            h[0]=a.x; h[1]=a.y; h[2]=a.z; h[3]=a.w;
            h[4]=b.x; h[5]=b.y; h[6]=b.z; h[7]=b.w;
        }
    }
}

// Build 24-wide window w[0..23] (cols col0-8 .. col0+15) from own v[8] and
// halo h[8] via 16 independent shuffles.
__device__ __forceinline__ void window24(const float v[8], const float h[8],
                                         int lane, float w[24]) {
    #pragma unroll
    for (int j = 0; j < 8; j++) w[8 + j] = v[j];
    #pragma unroll
    for (int j = 0; j < 8; j++) {
        float t = __shfl_up_sync(FULLM, v[j], 1);
        w[j] = (lane == 0) ? h[j] : t;
    }
    #pragma unroll
    for (int j = 0; j < 8; j++) {
        float t = __shfl_down_sync(FULLM, v[j], 1);
        w[16 + j] = (lane == 31) ? h[j] : t;
    }
}

// Stage-A row visit: accumulate (SGN) h-box of {x, y, x*x, x*y} into s0..s3.
template<int SGN>
__device__ __forceinline__ void visitA(const float* __restrict__ xr,
                                       const float* __restrict__ yr,
                                       int C, int lane,
                                       float s0[8], float s1[8],
                                       float s2[8], float s3[8]) {
    float vx[8], hx[8], vy[8], hy[8];
    load_strip(xr, C, lane, vx, hx);
    load_strip(yr, C, lane, vy, hy);
    float wx[24], wy[24];
    window24(vx, hx, lane, wx);
    window24(vy, hy, lane, wy);

    float sx = 0.f, sy = 0.f, sxx = 0.f, sxy = 0.f;
    #pragma unroll
    for (int j = 0; j < 17; j++) {
        float a = wx[j], b = wy[j];
        sx += a; sy += b;
        sxx = fmaf(a, a, sxx);
        sxy = fmaf(a, b, sxy);
    }
    #pragma unroll
    for (int k = 0; k < 8; k++) {
        if (k > 0) {
            float ao = wx[k-1], bo = wy[k-1];
            float an = wx[k+16], bn = wy[k+16];
            sx  += an - ao;
            sy  += bn - bo;
            sxx += an*an - ao*ao;
            sxy += an*bn - ao*bo;
        }
        if (SGN > 0) { s0[k] += sx; s1[k] += sy; s2[k] += sxx; s3[k] += sxy; }
        else         { s0[k] -= sx; s1[k] -= sy; s2[k] -= sxx; s3[k] -= sxy; }
    }
}

// kB primitive: chain-free prefix/suffix exchange per series.
template<int SGN>
__device__ __forceinline__ void box_acc(const float w[8], const float hw[8],
                                        int lane, float s[8]) {
    float p[9];
    p[0] = 0.0f;
    #pragma unroll
    for (int j = 0; j < 8; j++) p[j + 1] = p[j] + w[j];
    float U = p[8];

    float sufL[8], preR[8];
    #pragma unroll
    for (int j = 0; j < 8; j++) {
        sufL[j] = __shfl_up_sync(FULLM, U - p[j], 1);
        preR[j] = __shfl_down_sync(FULLM, p[j + 1], 1);
    }
    if (lane == 0) {
        float acc = 0.0f;
        #pragma unroll
        for (int j = 7; j >= 0; j--) { acc += hw[j]; sufL[j] = acc; }
    }
    if (lane == 31) {
        float acc = 0.0f;
        #pragma unroll
        for (int j = 0; j < 8; j++) { acc += hw[j]; preR[j] = acc; }
    }
    #pragma unroll
    for (int j = 0; j < 8; j++) {
        float b = (sufL[j] + U) + preR[j];
        if (SGN > 0) s[j] += b; else s[j] -= b;
    }
}

template<int SGN>
__device__ __forceinline__ void visitB(const float* __restrict__ ar,
                                       const float* __restrict__ br,
                                       int C, int lane,
                                       float sa[8], float sb[8]) {
    float va[8], ha[8], vb[8], hb[8];
    load_strip(ar, C, lane, va, ha);
    load_strip(br, C, lane, vb, hb);
    box_acc<SGN>(va, ha, lane, sa);
    box_acc<SGN>(vb, hb, lane, sb);
}

// ---------------------------------------------------------------------------
__global__ void __launch_bounds__(TPB) kA(const float* __restrict__ x,
                                          const float* __restrict__ y) {
    int img  = blockIdx.y;
    int s    = blockIdx.x * SEGR;
    int warp = threadIdx.x >> 5;
    int lane = threadIdx.x & 31;
    int C    = warp << 8;
    int col0 = C + lane * 8;
    const float* xb = x + img * HW;
    const float* yb = y + img * HW;

    float s0[8], s1[8], s2[8], s3[8];
    #pragma unroll
    for (int j = 0; j < 8; j++) { s0[j]=0.f; s1[j]=0.f; s2[j]=0.f; s3[j]=0.f; }

    for (int r = max(0, s - RAD); r <= s + RAD; r++)
        visitA<+1>(xb + r * W, yb + r * W, C, lane, s0, s1, s2, s3);

    float inv_nx[8];
    #pragma unroll
    for (int j = 0; j < 8; j++) {
        int c = col0 + j;
        inv_nx[j] = __frcp_rn((float)(min(W - 1, c + RAD) - max(0, c - RAD) + 1));
    }

    float* ga = g_a + img * HW;
    float* gb = g_b + img * HW;

    for (int o = s; o < s + SEGR; o++) {
        float inv_ny = __frcp_rn((float)(min(Hh - 1, o + RAD) - max(0, o - RAD) + 1));
        float ra[8], rb[8];
        #pragma unroll
        for (int j = 0; j < 8; j++) {
            float invN = inv_nx[j] * inv_ny;
            float mx = s0[j] * invN, my = s1[j] * invN;
            float varx = fmaf(-mx, mx, s2[j] * invN);
            float cov  = fmaf(-mx, my, s3[j] * invN);
            float a = __fdividef(cov, varx + EPSF);
            ra[j] = a;
            rb[j] = fmaf(-a, mx, my);
        }
        #pragma unroll
        for (int q = 0; q < 2; q++) {
            float4 av, bv;
            av.x = ra[4*q+0]; av.y = ra[4*q+1]; av.z = ra[4*q+2]; av.w = ra[4*q+3];
            bv.x = rb[4*q+0]; bv.y = rb[4*q+1]; bv.z = rb[4*q+2]; bv.w = rb[4*q+3];
            *(float4*)(ga + o * W + col0 + 4*q) = av;
            *(float4*)(gb + o * W + col0 + 4*q) = bv;
        }

        int lead = o + RAD + 1, trail = o - RAD;
        if (lead < Hh)
            visitA<+1>(xb + lead * W, yb + lead * W, C, lane, s0, s1, s2, s3);
        if (trail >= 0)
            visitA<-1>(xb + trail * W, yb + trail * W, C, lane, s0, s1, s2, s3);
    }
}

// ---------------------------------------------------------------------------
__global__ void __launch_bounds__(TPB) kB(const float* __restrict__ x,
                                          float* __restrict__ out) {
    int img  = blockIdx.y;
    int s    = blockIdx.x * SEGR;
    int warp = threadIdx.x >> 5;
    int lane = threadIdx.x & 31;
    int C    = warp << 8;
    int col0 = C + lane * 8;
    const float* ab = g_a + img * HW;
    const float* bb = g_b + img * HW;
    const float* xb = x + img * HW;
    float* ob = out + img * HW;

    float sa[8], sb[8];
    #pragma unroll
    for (int j = 0; j < 8; j++) { sa[j]=0.f; sb[j]=0.f; }

    for (int r = max(0, s - RAD); r <= s + RAD; r++)
        visitB<+1>(ab + r * W, bb + r * W, C, lane, sa, sb);

    float inv_nx[8];
    #pragma unroll
    for (int j = 0; j < 8; j++) {
        int c = col0 + j;
        inv_nx[j] = __frcp_rn((float)(min(W - 1, c + RAD) - max(0, c - RAD) + 1));
    }

    for (int o = s; o < s + SEGR; o++) {
        float inv_ny = __frcp_rn((float)(min(Hh - 1, o + RAD) - max(0, o - RAD) + 1));
        #pragma unroll
        for (int q = 0; q < 2; q++) {
            float4 xv = *(const float4*)(xb + o * W + col0 + 4*q);
            float xs[4] = {xv.x, xv.y, xv.z, xv.w};
            float os[4];
            #pragma unroll
            for (int j = 0; j < 4; j++) {
                int k = 4*q + j;
                float invN = inv_nx[k] * inv_ny;
                os[j] = fmaf(sa[k] * invN, xs[j], sb[k] * invN);
            }
            float4 ov;
            ov.x = os[0]; ov.y = os[1]; ov.z = os[2]; ov.w = os[3];
            *(float4*)(ob + o * W + col0 + 4*q) = ov;
        }

        int lead = o + RAD + 1, trail = o - RAD;
        if (lead < Hh)
            visitB<+1>(ab + lead * W, bb + lead * W, C, lane, sa, sb);
        if (trail >= 0)
            visitB<-1>(ab + trail * W, bb + trail * W, C, lane, sa, sb);
    }
}

extern "C" void kernel_launch(void* const* d_in, const int* in_sizes, int n_in,
                              void* d_out, int out_size) {
    const float* x = (const float*)d_in[0];
    const float* y = (const float*)d_in[1];
    float* out = (float*)d_out;

    dim3 grid(SEGS, IMGS);
    kA<<<grid, TPB>>>(x, y);
    kB<<<grid, TPB>>>(x, out);
}

// round 8
// speedup vs baseline: 1.3672x; 1.1161x over previous
#include <cuda_runtime.h>
#include <cuda_fp16.h>

// Guided filter, RADIUS=8, EPS=0.01, (8,3,1024,1024) fp32.
// kA: raw-value warp exchange, 24-wide register window, 4 series local,
//     writes (a,b) packed as half2 (one 32-bit word per pixel).
// kB: chain-free prefix exchange on a,b decoded from half2 scratch.
// Vertical sliding box with trail recompute in both.

#define W     1024
#define Hh    1024
#define IMGS  24
#define HW    (Hh * W)
#define TOTAL (IMGS * HW)
#define RAD   8
#define EPSF  0.01f
#define SEGR_A 16
#define SEGS_A (Hh / SEGR_A)
#define SEGR_B 32
#define SEGS_B (Hh / SEGR_B)
#define TPB   128               // 4 warps; warp w owns cols [256w, 256w+255]
#define FULLM 0xffffffffu

__device__ __align__(16) __half2 g_ab[TOTAL];   // packed (a,b) per pixel

__device__ __forceinline__ void dec_h2(unsigned int u, float& a, float& b) {
    __half2 h = *reinterpret_cast<__half2*>(&u);
    float2 f = __half22float2(h);
    a = f.x; b = f.y;
}
__device__ __forceinline__ unsigned int pack_h2(float a, float b) {
    __half2 h = __floats2half2_rn(a, b);
    return *reinterpret_cast<unsigned int*>(&h);
}

// ---------------- stage A (fp32 inputs) ------------------------------------
__device__ __forceinline__ void load_strip(const float* __restrict__ r, int C,
                                           int lane, float v[8], float h[8]) {
    int col0 = C + lane * 8;
    float4 p0 = *(const float4*)(r + col0);
    float4 p1 = *(const float4*)(r + col0 + 4);
    v[0]=p0.x; v[1]=p0.y; v[2]=p0.z; v[3]=p0.w;
    v[4]=p1.x; v[5]=p1.y; v[6]=p1.z; v[7]=p1.w;
    #pragma unroll
    for (int j = 0; j < 8; j++) h[j] = 0.0f;
    if (lane == 0) {
        if (C > 0) {
            float4 a = *(const float4*)(r + C - 8);
            float4 b = *(const float4*)(r + C - 4);
            h[0]=a.x; h[1]=a.y; h[2]=a.z; h[3]=a.w;
            h[4]=b.x; h[5]=b.y; h[6]=b.z; h[7]=b.w;
        }
    } else if (lane == 31) {
        if (C + 256 < W) {
            float4 a = *(const float4*)(r + C + 256);
            float4 b = *(const float4*)(r + C + 260);
            h[0]=a.x; h[1]=a.y; h[2]=a.z; h[3]=a.w;
            h[4]=b.x; h[5]=b.y; h[6]=b.z; h[7]=b.w;
        }
    }
}

__device__ __forceinline__ void window24(const float v[8], const float h[8],
                                         int lane, float w[24]) {
    #pragma unroll
    for (int j = 0; j < 8; j++) w[8 + j] = v[j];
    #pragma unroll
    for (int j = 0; j < 8; j++) {
        float t = __shfl_up_sync(FULLM, v[j], 1);
        w[j] = (lane == 0) ? h[j] : t;
    }
    #pragma unroll
    for (int j = 0; j < 8; j++) {
        float t = __shfl_down_sync(FULLM, v[j], 1);
        w[16 + j] = (lane == 31) ? h[j] : t;
    }
}

template<int SGN>
__device__ __forceinline__ void visitA(const float* __restrict__ xr,
                                       const float* __restrict__ yr,
                                       int C, int lane,
                                       float s0[8], float s1[8],
                                       float s2[8], float s3[8]) {
    float vx[8], hx[8], vy[8], hy[8];
    load_strip(xr, C, lane, vx, hx);
    load_strip(yr, C, lane, vy, hy);
    float wx[24], wy[24];
    window24(vx, hx, lane, wx);
    window24(vy, hy, lane, wy);

    float sx = 0.f, sy = 0.f, sxx = 0.f, sxy = 0.f;
    #pragma unroll
    for (int j = 0; j < 17; j++) {
        float a = wx[j], b = wy[j];
        sx += a; sy += b;
        sxx = fmaf(a, a, sxx);
        sxy = fmaf(a, b, sxy);
    }
    #pragma unroll
    for (int k = 0; k < 8; k++) {
        if (k > 0) {
            float ao = wx[k-1], bo = wy[k-1];
            float an = wx[k+16], bn = wy[k+16];
            sx  += an - ao;
            sy  += bn - bo;
            sxx += an*an - ao*ao;
            sxy += an*bn - ao*bo;
        }
        if (SGN > 0) { s0[k] += sx; s1[k] += sy; s2[k] += sxx; s3[k] += sxy; }
        else         { s0[k] -= sx; s1[k] -= sy; s2[k] -= sxx; s3[k] -= sxy; }
    }
}

// ---------------- stage B (half2 scratch) ----------------------------------
// Load own 8 (a,b) pairs + halo pairs on lanes 0/31.
__device__ __forceinline__ void load_strip_h2(const __half2* __restrict__ r, int C,
                                              int lane,
                                              float va[8], float vb[8],
                                              float ha[8], float hb[8]) {
    int col0 = C + lane * 8;
    uint4 p0 = *(const uint4*)(r + col0);
    uint4 p1 = *(const uint4*)(r + col0 + 4);
    dec_h2(p0.x, va[0], vb[0]); dec_h2(p0.y, va[1], vb[1]);
    dec_h2(p0.z, va[2], vb[2]); dec_h2(p0.w, va[3], vb[3]);
    dec_h2(p1.x, va[4], vb[4]); dec_h2(p1.y, va[5], vb[5]);
    dec_h2(p1.z, va[6], vb[6]); dec_h2(p1.w, va[7], vb[7]);
    #pragma unroll
    for (int j = 0; j < 8; j++) { ha[j] = 0.0f; hb[j] = 0.0f; }
    if (lane == 0) {
        if (C > 0) {
            uint4 q0 = *(const uint4*)(r + C - 8);
            uint4 q1 = *(const uint4*)(r + C - 4);
            dec_h2(q0.x, ha[0], hb[0]); dec_h2(q0.y, ha[1], hb[1]);
            dec_h2(q0.z, ha[2], hb[2]); dec_h2(q0.w, ha[3], hb[3]);
            dec_h2(q1.x, ha[4], hb[4]); dec_h2(q1.y, ha[5], hb[5]);
            dec_h2(q1.z, ha[6], hb[6]); dec_h2(q1.w, ha[7], hb[7]);
        }
    } else if (lane == 31) {
        if (C + 256 < W) {
            uint4 q0 = *(const uint4*)(r + C + 256);
            uint4 q1 = *(const uint4*)(r + C + 260);
            dec_h2(q0.x, ha[0], hb[0]); dec_h2(q0.y, ha[1], hb[1]);
            dec_h2(q0.z, ha[2], hb[2]); dec_h2(q0.w, ha[3], hb[3]);
            dec_h2(q1.x, ha[4], hb[4]); dec_h2(q1.y, ha[5], hb[5]);
            dec_h2(q1.z, ha[6], hb[6]); dec_h2(q1.w, ha[7], hb[7]);
        }
    }
}

// Chain-free prefix/suffix exchange per series.
template<int SGN>
__device__ __forceinline__ void box_acc(const float w[8], const float hw[8],
                                        int lane, float s[8]) {
    float p[9];
    p[0] = 0.0f;
    #pragma unroll
    for (int j = 0; j < 8; j++) p[j + 1] = p[j] + w[j];
    float U = p[8];

    float sufL[8], preR[8];
    #pragma unroll
    for (int j = 0; j < 8; j++) {
        sufL[j] = __shfl_up_sync(FULLM, U - p[j], 1);
        preR[j] = __shfl_down_sync(FULLM, p[j + 1], 1);
    }
    if (lane == 0) {
        float acc = 0.0f;
        #pragma unroll
        for (int j = 7; j >= 0; j--) { acc += hw[j]; sufL[j] = acc; }
    }
    if (lane == 31) {
        float acc = 0.0f;
        #pragma unroll
        for (int j = 0; j < 8; j++) { acc += hw[j]; preR[j] = acc; }
    }
    #pragma unroll
    for (int j = 0; j < 8; j++) {
        float b = (sufL[j] + U) + preR[j];
        if (SGN > 0) s[j] += b; else s[j] -= b;
    }
}

template<int SGN>
__device__ __forceinline__ void visitB(const __half2* __restrict__ abr,
                                       int C, int lane,
                                       float sa[8], float sb[8]) {
    float va[8], vb[8], ha[8], hb[8];
    load_strip_h2(abr, C, lane, va, vb, ha, hb);
    box_acc<SGN>(va, ha, lane, sa);
    box_acc<SGN>(vb, hb, lane, sb);
}

// ---------------------------------------------------------------------------
__global__ void __launch_bounds__(TPB) kA(const float* __restrict__ x,
                                          const float* __restrict__ y) {
    int img  = blockIdx.y;
    int s    = blockIdx.x * SEGR_A;
    int warp = threadIdx.x >> 5;
    int lane = threadIdx.x & 31;
    int C    = warp << 8;
    int col0 = C + lane * 8;
    const float* xb = x + img * HW;
    const float* yb = y + img * HW;

    float s0[8], s1[8], s2[8], s3[8];
    #pragma unroll
    for (int j = 0; j < 8; j++) { s0[j]=0.f; s1[j]=0.f; s2[j]=0.f; s3[j]=0.f; }

    for (int r = max(0, s - RAD); r <= s + RAD; r++)
        visitA<+1>(xb + r * W, yb + r * W, C, lane, s0, s1, s2, s3);

    float inv_nx[8];
    #pragma unroll
    for (int j = 0; j < 8; j++) {
        int c = col0 + j;
        inv_nx[j] = __frcp_rn((float)(min(W - 1, c + RAD) - max(0, c - RAD) + 1));
    }

    __half2* gab = g_ab + img * HW;

    for (int o = s; o < s + SEGR_A; o++) {
        float inv_ny = __frcp_rn((float)(min(Hh - 1, o + RAD) - max(0, o - RAD) + 1));
        unsigned int pk[8];
        #pragma unroll
        for (int j = 0; j < 8; j++) {
            float invN = inv_nx[j] * inv_ny;
            float mx = s0[j] * invN, my = s1[j] * invN;
            float varx = fmaf(-mx, mx, s2[j] * invN);
            float cov  = fmaf(-mx, my, s3[j] * invN);
            float a = __fdividef(cov, varx + EPSF);
            float b = fmaf(-a, mx, my);
            pk[j] = pack_h2(a, b);
        }
        uint4 u0, u1;
        u0.x = pk[0]; u0.y = pk[1]; u0.z = pk[2]; u0.w = pk[3];
        u1.x = pk[4]; u1.y = pk[5]; u1.z = pk[6]; u1.w = pk[7];
        *(uint4*)(gab + o * W + col0)     = u0;
        *(uint4*)(gab + o * W + col0 + 4) = u1;

        int lead = o + RAD + 1, trail = o - RAD;
        if (lead < Hh)
            visitA<+1>(xb + lead * W, yb + lead * W, C, lane, s0, s1, s2, s3);
        if (trail >= 0)
            visitA<-1>(xb + trail * W, yb + trail * W, C, lane, s0, s1, s2, s3);
    }
}

// ---------------------------------------------------------------------------
__global__ void __launch_bounds__(TPB) kB(const float* __restrict__ x,
                                          float* __restrict__ out) {
    int img  = blockIdx.y;
    int s    = blockIdx.x * SEGR_B;
    int warp = threadIdx.x >> 5;
    int lane = threadIdx.x & 31;
    int C    = warp << 8;
    int col0 = C + lane * 8;
    const __half2* abr = g_ab + img * HW;
    const float* xb = x + img * HW;
    float* ob = out + img * HW;

    float sa[8], sb[8];
    #pragma unroll
    for (int j = 0; j < 8; j++) { sa[j]=0.f; sb[j]=0.f; }

    for (int r = max(0, s - RAD); r <= s + RAD; r++)
        visitB<+1>(abr + r * W, C, lane, sa, sb);

    float inv_nx[8];
    #pragma unroll
    for (int j = 0; j < 8; j++) {
        int c = col0 + j;
        inv_nx[j] = __frcp_rn((float)(min(W - 1, c + RAD) - max(0, c - RAD) + 1));
    }

    for (int o = s; o < s + SEGR_B; o++) {
        float inv_ny = __frcp_rn((float)(min(Hh - 1, o + RAD) - max(0, o - RAD) + 1));
        #pragma unroll
        for (int q = 0; q < 2; q++) {
            float4 xv = *(const float4*)(xb + o * W + col0 + 4*q);
            float xs[4] = {xv.x, xv.y, xv.z, xv.w};
            float os[4];
            #pragma unroll
            for (int j = 0; j < 4; j++) {
                int k = 4*q + j;
                float invN = inv_nx[k] * inv_ny;
                os[j] = fmaf(sa[k] * invN, xs[j], sb[k] * invN);
            }
            float4 ov;
            ov.x = os[0]; ov.y = os[1]; ov.z = os[2]; ov.w = os[3];
            *(float4*)(ob + o * W + col0 + 4*q) = ov;
        }

        int lead = o + RAD + 1, trail = o - RAD;
        if (lead < Hh)
            visitB<+1>(abr + lead * W, C, lane, sa, sb);
        if (trail >= 0)
            visitB<-1>(abr + trail * W, C, lane, sa, sb);
    }
}

extern "C" void kernel_launch(void* const* d_in, const int* in_sizes, int n_in,
                              void* d_out, int out_size) {
    const float* x = (const float*)d_in[0];
    const float* y = (const float*)d_in[1];
    float* out = (float*)d_out;

    dim3 gridA(SEGS_A, IMGS);
    dim3 gridB(SEGS_B, IMGS);
    kA<<<gridA, TPB>>>(x, y);
    kB<<<gridB, TPB>>>(x, out);
}